// round 10
// baseline (speedup 1.0000x reference)
#include <cuda_runtime.h>
#include <cuda_fp16.h>
#include <cstdint>
#include <math.h>

#define N_NODES_MAX 100000
#define E_MAX       1600000
#define D1 64
#define D2 32
#define SCAN_B 512
#define NB_MAX 256
#define GB_NODES 64     // nodes per gemm block
#define IN_STRIDE 72    // floats

// Scratch (no allocations allowed)
__device__ __half g_xh  [(size_t)N_NODES_MAX * D1];
__device__ __half g_aggh[(size_t)N_NODES_MAX * D1];  // layer1 aggregated means (fp16)
__device__ __half g_x2th[(size_t)N_NODES_MAX * D2];
__device__ int    g_cnt [N_NODES_MAX];   // zeroed by scan (self-restoring)
__device__ int    g_row [N_NODES_MAX + 1];
__device__ int    g_cur [N_NODES_MAX];
__device__ int    g_csr [E_MAX];
__device__ int    g_agg [NB_MAX];        // lookback publish slots (0 = empty)

// ---------------------------------------------------------------------------
__device__ __forceinline__ void unpack2(unsigned long long v, float& lo, float& hi) {
    unsigned int a, b;
    asm("mov.b64 {%0, %1}, %2;" : "=r"(a), "=r"(b) : "l"(v));
    lo = __uint_as_float(a);
    hi = __uint_as_float(b);
}
__device__ __forceinline__ unsigned long long fma2(unsigned long long a,
                                                   unsigned long long b,
                                                   unsigned long long c) {
    unsigned long long d;
    asm("fma.rn.f32x2 %0, %1, %2, %3;" : "=l"(d) : "l"(a), "l"(b), "l"(c));
    return d;
}

// ---------------------------------------------------------------------------
__global__ void conv_hist_kernel(const float4* __restrict__ x4,
                                 uint2* __restrict__ xh,
                                 const int* __restrict__ dst,
                                 int* __restrict__ cnt,
                                 int n4, int E) {
    int i = blockIdx.x * blockDim.x + threadIdx.x;
    if (i < n4) {
        float4 v = x4[i];
        __half2 a = __floats2half2_rn(v.x, v.y);
        __half2 b = __floats2half2_rn(v.z, v.w);
        uint2 o;
        o.x = *reinterpret_cast<unsigned int*>(&a);
        o.y = *reinterpret_cast<unsigned int*>(&b);
        xh[i] = o;
    }
    if (i < E) atomicAdd(&cnt[dst[i]], 1);
}

// ---------------------------------------------------------------------------
__global__ void __launch_bounds__(SCAN_B)
scan_kernel(int* __restrict__ cnt, int* __restrict__ row, int* __restrict__ cur,
            int* __restrict__ agg, int N, int E) {
    __shared__ int s[SCAN_B];
    int t = threadIdx.x;
    int b = blockIdx.x;
    int i = b * SCAN_B + t;
    int v = (i < N) ? cnt[i] : 0;
    if (i < N) cnt[i] = 0;
    s[t] = v;
    __syncthreads();
#pragma unroll
    for (int off = 1; off < SCAN_B; off <<= 1) {
        int u = 0;
        if (t >= off) u = s[t - off];
        __syncthreads();
        if (t >= off) s[t] += u;
        __syncthreads();
    }
    int incl = s[t];
    if (t == 0) atomicExch(&agg[b], s[SCAN_B - 1] + 1);

    int acc = 0;
    for (int idx = t; idx < b; idx += SCAN_B) {
        volatile int* p = &agg[idx];
        int a;
        while ((a = *p) == 0) { }
        acc += a - 1;
    }
    __syncthreads();
    s[t] = acc;
    __syncthreads();
#pragma unroll
    for (int off = SCAN_B / 2; off > 0; off >>= 1) {
        if (t < off) s[t] += s[t + off];
        __syncthreads();
    }
    int offset = s[0];
    if (i < N) {
        int r = offset + incl - v;
        row[i] = r;
        cur[i] = r;
    }
    if (i == N) row[N] = E;
}

// ---------------------------------------------------------------------------
__global__ void fill_kernel(const int* __restrict__ src, const int* __restrict__ dst,
                            int* __restrict__ cur, int* __restrict__ csr,
                            int* __restrict__ agg, int E) {
    int i = blockIdx.x * blockDim.x + threadIdx.x;
    if (i < NB_MAX) agg[i] = 0;
    if (i < E) {
        int d = dst[i];
        int p = atomicAdd(&cur[d], 1);
        csr[p] = src[i];
    }
}

// ---------------------------------------------------------------------------
__device__ __forceinline__ void acc_h8(float* acc, uint4 v) {
    float2 f;
    f = __half22float2(*reinterpret_cast<__half2*>(&v.x)); acc[0] += f.x; acc[1] += f.y;
    f = __half22float2(*reinterpret_cast<__half2*>(&v.y)); acc[2] += f.x; acc[3] += f.y;
    f = __half22float2(*reinterpret_cast<__half2*>(&v.z)); acc[4] += f.x; acc[5] += f.y;
    f = __half22float2(*reinterpret_cast<__half2*>(&v.w)); acc[6] += f.x; acc[7] += f.y;
}

// Layer-1 gather only: agg = mean(xh[neighbors]), fp16 in / fp16 out.
// 8 lanes per node, 16B per lane, no smem -> max occupancy & MLP.
__global__ void __launch_bounds__(512)
gather1_kernel(const __half* __restrict__ xh,
               const int*    __restrict__ csr,
               const int*    __restrict__ row,
               __half*       __restrict__ aggh,   // [N,64] fp16
               int N) {
    int grp = threadIdx.x >> 3;       // 64 nodes per block
    int lane = threadIdx.x & 7;
    int node = blockIdx.x * 64 + grp;
    if (node >= N) node = N - 1;

    int beg = row[node], end = row[node + 1];
    const uint4* xh4 = reinterpret_cast<const uint4*>(xh);  // row stride 8

    float acc[8];
#pragma unroll
    for (int i = 0; i < 8; i++) acc[i] = 0.f;

    int e = beg;
    for (; e + 3 < end; e += 4) {
        int s0 = csr[e], s1 = csr[e + 1], s2 = csr[e + 2], s3 = csr[e + 3];
        uint4 v0 = xh4[(size_t)s0 * 8 + lane];
        uint4 v1 = xh4[(size_t)s1 * 8 + lane];
        uint4 v2 = xh4[(size_t)s2 * 8 + lane];
        uint4 v3 = xh4[(size_t)s3 * 8 + lane];
        acc_h8(acc, v0); acc_h8(acc, v1); acc_h8(acc, v2); acc_h8(acc, v3);
    }
    for (; e < end; e++) {
        uint4 v0 = xh4[(size_t)csr[e] * 8 + lane];
        acc_h8(acc, v0);
    }
    float inv = 1.0f / fmaxf((float)(end - beg), 1.0f);
    __half2 h0 = __floats2half2_rn(acc[0] * inv, acc[1] * inv);
    __half2 h1 = __floats2half2_rn(acc[2] * inv, acc[3] * inv);
    __half2 h2 = __floats2half2_rn(acc[4] * inv, acc[5] * inv);
    __half2 h3 = __floats2half2_rn(acc[6] * inv, acc[7] * inv);
    uint4 o;
    o.x = *reinterpret_cast<unsigned int*>(&h0);
    o.y = *reinterpret_cast<unsigned int*>(&h1);
    o.z = *reinterpret_cast<unsigned int*>(&h2);
    o.w = *reinterpret_cast<unsigned int*>(&h3);
    reinterpret_cast<uint4*>(aggh)[(size_t)node * 8 + lane] = o;
}

// ---------------------------------------------------------------------------
// GEMM kernel: x2t = relu(agg@W1+b1) @ W2 (fp16 store). Streaming, regular.
// Block = 256 threads, 64 nodes. k-pair FFMA2, W pre-packed k-pair-major.
__global__ void __launch_bounds__(256, 4)
gemm1_kernel(const __half* __restrict__ aggh,  // [N,64] fp16
             const float*  __restrict__ W1,    // [64,64] (k, j)
             const float*  __restrict__ b1,    // [64]
             const float*  __restrict__ W2,    // [64,32] (k, j)
             __half*       __restrict__ x2th,  // [N,32] fp16
             int N) {
    __shared__ float Wp1[(D1 / 2) * D1 * 2];   // [kp][j][2]
    __shared__ float Wp2[(D1 / 2) * D2 * 2];
    __shared__ float b1s[D1];
    __shared__ float in_s[GB_NODES][IN_STRIDE];

    for (int i = threadIdx.x; i < D1 * D1; i += 256) {
        int k = i >> 6, j = i & 63;
        Wp1[(k >> 1) * (D1 * 2) + j * 2 + (k & 1)] = W1[i];
    }
    for (int i = threadIdx.x; i < D1 * D2; i += 256) {
        int k = i >> 5, j = i & 31;
        Wp2[(k >> 1) * (D2 * 2) + j * 2 + (k & 1)] = W2[i];
    }
    if (threadIdx.x < D1) b1s[threadIdx.x] = b1[threadIdx.x];

    // Load agg tile (coalesced): 4 threads per node, 16 halves each.
    {
        int nl = threadIdx.x >> 2;       // 0..63
        int ch = threadIdx.x & 3;        // 16-half chunk
        int node = blockIdx.x * GB_NODES + nl;
        if (node >= N) node = N - 1;
        const uint4* ap = reinterpret_cast<const uint4*>(aggh) + (size_t)node * 8 + ch * 2;
        uint4 v0 = ap[0];
        uint4 v1 = ap[1];
        float f[16];
        float2 t;
        t = __half22float2(*reinterpret_cast<__half2*>(&v0.x)); f[0] = t.x; f[1] = t.y;
        t = __half22float2(*reinterpret_cast<__half2*>(&v0.y)); f[2] = t.x; f[3] = t.y;
        t = __half22float2(*reinterpret_cast<__half2*>(&v0.z)); f[4] = t.x; f[5] = t.y;
        t = __half22float2(*reinterpret_cast<__half2*>(&v0.w)); f[6] = t.x; f[7] = t.y;
        t = __half22float2(*reinterpret_cast<__half2*>(&v1.x)); f[8] = t.x; f[9] = t.y;
        t = __half22float2(*reinterpret_cast<__half2*>(&v1.y)); f[10] = t.x; f[11] = t.y;
        t = __half22float2(*reinterpret_cast<__half2*>(&v1.z)); f[12] = t.x; f[13] = t.y;
        t = __half22float2(*reinterpret_cast<__half2*>(&v1.w)); f[14] = t.x; f[15] = t.y;
        float4* dst4 = reinterpret_cast<float4*>(&in_s[nl][ch * 16]);
#pragma unroll
        for (int q = 0; q < 4; q++)
            dst4[q] = make_float4(f[q * 4], f[q * 4 + 1], f[q * 4 + 2], f[q * 4 + 3]);
    }
    __syncthreads();

    int jg = threadIdx.x & 15;
    int ng = threadIdx.x >> 4;
    int j  = jg * 4;
    int nb0 = ng * 4;

    // Phase B: x1 = relu(agg @ W1 + b1), k-pair FFMA2
    unsigned long long acc[4][4];
#pragma unroll
    for (int nn = 0; nn < 4; nn++)
#pragma unroll
        for (int jj = 0; jj < 4; jj++) acc[nn][jj] = 0ull;

#pragma unroll 8
    for (int kp = 0; kp < D1 / 2; kp++) {
        ulonglong2 wa = *reinterpret_cast<const ulonglong2*>(&Wp1[kp * (D1 * 2) + j * 2]);
        ulonglong2 wb = *reinterpret_cast<const ulonglong2*>(&Wp1[kp * (D1 * 2) + j * 2 + 4]);
#pragma unroll
        for (int nn = 0; nn < 4; nn++) {
            unsigned long long xv =
                *reinterpret_cast<const unsigned long long*>(&in_s[nb0 + nn][kp * 2]);
            acc[nn][0] = fma2(xv, wa.x, acc[nn][0]);
            acc[nn][1] = fma2(xv, wa.y, acc[nn][1]);
            acc[nn][2] = fma2(xv, wb.x, acc[nn][2]);
            acc[nn][3] = fma2(xv, wb.y, acc[nn][3]);
        }
    }
    float x1v[4][4];
#pragma unroll
    for (int nn = 0; nn < 4; nn++) {
#pragma unroll
        for (int jj = 0; jj < 4; jj++) {
            float lo, hi;
            unpack2(acc[nn][jj], lo, hi);
            x1v[nn][jj] = fmaxf(lo + hi + b1s[j + jj], 0.f);
        }
    }
    __syncthreads();
#pragma unroll
    for (int nn = 0; nn < 4; nn++)
        *reinterpret_cast<float4*>(&in_s[nb0 + nn][j]) =
            make_float4(x1v[nn][0], x1v[nn][1], x1v[nn][2], x1v[nn][3]);
    __syncthreads();

    // Phase C: x2t = x1 @ W2 (fp16 store), k-pair FFMA2
    int j2 = jg * 2;
    unsigned long long pacc[4][2];
#pragma unroll
    for (int nn = 0; nn < 4; nn++) { pacc[nn][0] = 0ull; pacc[nn][1] = 0ull; }

#pragma unroll 8
    for (int kp = 0; kp < D1 / 2; kp++) {
        ulonglong2 w = *reinterpret_cast<const ulonglong2*>(&Wp2[kp * (D2 * 2) + j2 * 2]);
#pragma unroll
        for (int nn = 0; nn < 4; nn++) {
            unsigned long long xv =
                *reinterpret_cast<const unsigned long long*>(&in_s[nb0 + nn][kp * 2]);
            pacc[nn][0] = fma2(xv, w.x, pacc[nn][0]);
            pacc[nn][1] = fma2(xv, w.y, pacc[nn][1]);
        }
    }
#pragma unroll
    for (int nn = 0; nn < 4; nn++) {
        float l0, h0, l1, h1;
        unpack2(pacc[nn][0], l0, h0);
        unpack2(pacc[nn][1], l1, h1);
        int node = blockIdx.x * GB_NODES + nb0 + nn;
        if (node >= N) node = N - 1;
        *reinterpret_cast<__half2*>(x2th + (size_t)node * D2 + j2) =
            __floats2half2_rn(l0 + h0, l1 + h1);
    }
}

// ---------------------------------------------------------------------------
// Layer 2 + readout (fp16 gather). 8 lanes per node, 8B per lane.
__global__ void __launch_bounds__(512)
layer2_kernel(const __half* __restrict__ x2th,
              const int*    __restrict__ csr,
              const int*    __restrict__ row,
              const float*  __restrict__ b2,
              const float*  __restrict__ Wd,
              const float*  __restrict__ bd,
              float*        __restrict__ out,
              int N) {
    __shared__ float bs[D2];
    if (threadIdx.x < D2) bs[threadIdx.x] = b2[threadIdx.x];
    __syncthreads();

    int grp = threadIdx.x >> 3;
    int lane = threadIdx.x & 7;
    int node = blockIdx.x * 64 + grp;
    if (node >= N) node = N - 1;

    int beg = row[node], end = row[node + 1];
    const uint2* x2 = reinterpret_cast<const uint2*>(x2th);

    float a0 = 0.f, a1 = 0.f, a2 = 0.f, a3 = 0.f;
    int e = beg;
    for (; e + 3 < end; e += 4) {
        int s0 = csr[e], s1 = csr[e + 1], s2 = csr[e + 2], s3 = csr[e + 3];
        uint2 v0 = x2[(size_t)s0 * 8 + lane];
        uint2 v1 = x2[(size_t)s1 * 8 + lane];
        uint2 v2 = x2[(size_t)s2 * 8 + lane];
        uint2 v3 = x2[(size_t)s3 * 8 + lane];
        float2 f;
        f = __half22float2(*reinterpret_cast<__half2*>(&v0.x)); a0 += f.x; a1 += f.y;
        f = __half22float2(*reinterpret_cast<__half2*>(&v0.y)); a2 += f.x; a3 += f.y;
        f = __half22float2(*reinterpret_cast<__half2*>(&v1.x)); a0 += f.x; a1 += f.y;
        f = __half22float2(*reinterpret_cast<__half2*>(&v1.y)); a2 += f.x; a3 += f.y;
        f = __half22float2(*reinterpret_cast<__half2*>(&v2.x)); a0 += f.x; a1 += f.y;
        f = __half22float2(*reinterpret_cast<__half2*>(&v2.y)); a2 += f.x; a3 += f.y;
        f = __half22float2(*reinterpret_cast<__half2*>(&v3.x)); a0 += f.x; a1 += f.y;
        f = __half22float2(*reinterpret_cast<__half2*>(&v3.y)); a2 += f.x; a3 += f.y;
    }
    for (; e < end; e++) {
        uint2 v0 = x2[(size_t)csr[e] * 8 + lane];
        float2 f;
        f = __half22float2(*reinterpret_cast<__half2*>(&v0.x)); a0 += f.x; a1 += f.y;
        f = __half22float2(*reinterpret_cast<__half2*>(&v0.y)); a2 += f.x; a3 += f.y;
    }
    float inv = 1.0f / fmaxf((float)(end - beg), 1.0f);
    int j = lane * 4;
    float h0 = fmaxf(fmaf(a0, inv, bs[j + 0]), 0.f);
    float h1 = fmaxf(fmaf(a1, inv, bs[j + 1]), 0.f);
    float h2 = fmaxf(fmaf(a2, inv, bs[j + 2]), 0.f);
    float h3 = fmaxf(fmaf(a3, inv, bs[j + 3]), 0.f);

    float v = (h0 + h1) + (h2 + h3);
#pragma unroll
    for (int off = 4; off > 0; off >>= 1)
        v += __shfl_down_sync(0xffffffffu, v, off, 8);

    if (lane == 0) {
        float m = v * (1.0f / (float)D2);
        float z = fmaf(m, Wd[0], bd[0]);
        out[node] = 1.0f / (1.0f + expf(-z));
    }
}

// ---------------------------------------------------------------------------
extern "C" void kernel_launch(void* const* d_in, const int* in_sizes, int n_in,
                              void* d_out, int out_size) {
    const float* x   = (const float*)d_in[0];
    const int*   src = (const int*)  d_in[1];
    const int*   dst = (const int*)  d_in[2];
    const float* W1  = (const float*)d_in[3];
    const float* b1  = (const float*)d_in[4];
    const float* W2  = (const float*)d_in[5];
    const float* b2  = (const float*)d_in[6];
    const float* Wd  = (const float*)d_in[7];
    const float* bd  = (const float*)d_in[8];
    float* out = (float*)d_out;

    const int N = in_sizes[0] / D1;
    const int E = in_sizes[1];

    __half *xh, *aggh, *x2th;
    int *cnt, *row, *cur, *csr, *agg;
    cudaGetSymbolAddress((void**)&xh,   g_xh);
    cudaGetSymbolAddress((void**)&aggh, g_aggh);
    cudaGetSymbolAddress((void**)&x2th, g_x2th);
    cudaGetSymbolAddress((void**)&cnt,  g_cnt);
    cudaGetSymbolAddress((void**)&row,  g_row);
    cudaGetSymbolAddress((void**)&cur,  g_cur);
    cudaGetSymbolAddress((void**)&csr,  g_csr);
    cudaGetSymbolAddress((void**)&agg,  g_agg);

    const int nb = (N + SCAN_B - 1) / SCAN_B;
    const int n4 = N * (D1 / 4);
    const int big = (n4 > E) ? n4 : E;

    conv_hist_kernel<<<(big + 255) / 256, 256>>>(
        reinterpret_cast<const float4*>(x), reinterpret_cast<uint2*>(xh),
        dst, cnt, n4, E);
    scan_kernel<<<nb, SCAN_B>>>(cnt, row, cur, agg, N, E);
    fill_kernel<<<(E + 255) / 256, 256>>>(src, dst, cur, csr, agg, E);

    gather1_kernel<<<(N + 63) / 64, 512>>>(xh, csr, row, aggh, N);
    gemm1_kernel<<<(N + GB_NODES - 1) / GB_NODES, 256>>>(aggh, W1, b1, W2, x2th, N);
    layer2_kernel<<<(N + 63) / 64, 512>>>(x2th, csr, row, b2, Wd, bd, out, N);
}

// round 11
// speedup vs baseline: 1.4101x; 1.4101x over previous
#include <cuda_runtime.h>
#include <cuda_fp16.h>
#include <cstdint>
#include <math.h>

#define N_NODES_MAX 100000
#define E_MAX       1600000
#define D1 64
#define D2 32
#define SCAN_B 512
#define NB_MAX 256

// Scratch (no allocations allowed)
__device__ __half g_xh  [(size_t)N_NODES_MAX * D1];
__device__ __half g_aggh[(size_t)N_NODES_MAX * D1];
__device__ __half g_x2th[(size_t)N_NODES_MAX * D2];
__device__ int    g_cnt [N_NODES_MAX];   // zeroed by scan (self-restoring)
__device__ int    g_row [N_NODES_MAX + 1];
__device__ int    g_cur [N_NODES_MAX];
__device__ int    g_csr [E_MAX];
__device__ int    g_agg [NB_MAX];        // lookback publish slots (0 = empty)

// ---------------------------------------------------------------------------
// mma / ldmatrix primitives
__device__ __forceinline__ void ldsm_x4(unsigned& a0, unsigned& a1,
                                        unsigned& a2, unsigned& a3, unsigned addr) {
    asm volatile("ldmatrix.sync.aligned.m8n8.x4.shared.b16 {%0,%1,%2,%3}, [%4];"
                 : "=r"(a0), "=r"(a1), "=r"(a2), "=r"(a3) : "r"(addr));
}
__device__ __forceinline__ void ldsm_x2(unsigned& b0, unsigned& b1, unsigned addr) {
    asm volatile("ldmatrix.sync.aligned.m8n8.x2.shared.b16 {%0,%1}, [%2];"
                 : "=r"(b0), "=r"(b1) : "r"(addr));
}
__device__ __forceinline__ void mma16816(float* c,
                                         unsigned a0, unsigned a1, unsigned a2, unsigned a3,
                                         unsigned b0, unsigned b1) {
    asm volatile("mma.sync.aligned.m16n8k16.row.col.f32.f16.f16.f32 "
                 "{%0,%1,%2,%3}, {%4,%5,%6,%7}, {%8,%9}, {%0,%1,%2,%3};"
                 : "+f"(c[0]), "+f"(c[1]), "+f"(c[2]), "+f"(c[3])
                 : "r"(a0), "r"(a1), "r"(a2), "r"(a3), "r"(b0), "r"(b1));
}
__device__ __forceinline__ unsigned packh2(float a, float b) {
    __half2 h = __floats2half2_rn(a, b);
    return *reinterpret_cast<unsigned*>(&h);
}

// ---------------------------------------------------------------------------
__global__ void conv_hist_kernel(const float4* __restrict__ x4,
                                 uint2* __restrict__ xh,
                                 const int* __restrict__ dst,
                                 int* __restrict__ cnt,
                                 int n4, int E) {
    int i = blockIdx.x * blockDim.x + threadIdx.x;
    if (i < n4) {
        float4 v = x4[i];
        __half2 a = __floats2half2_rn(v.x, v.y);
        __half2 b = __floats2half2_rn(v.z, v.w);
        uint2 o;
        o.x = *reinterpret_cast<unsigned int*>(&a);
        o.y = *reinterpret_cast<unsigned int*>(&b);
        xh[i] = o;
    }
    if (i < E) atomicAdd(&cnt[dst[i]], 1);
}

// ---------------------------------------------------------------------------
__global__ void __launch_bounds__(SCAN_B)
scan_kernel(int* __restrict__ cnt, int* __restrict__ row, int* __restrict__ cur,
            int* __restrict__ agg, int N, int E) {
    __shared__ int s[SCAN_B];
    int t = threadIdx.x;
    int b = blockIdx.x;
    int i = b * SCAN_B + t;
    int v = (i < N) ? cnt[i] : 0;
    if (i < N) cnt[i] = 0;
    s[t] = v;
    __syncthreads();
#pragma unroll
    for (int off = 1; off < SCAN_B; off <<= 1) {
        int u = 0;
        if (t >= off) u = s[t - off];
        __syncthreads();
        if (t >= off) s[t] += u;
        __syncthreads();
    }
    int incl = s[t];
    if (t == 0) atomicExch(&agg[b], s[SCAN_B - 1] + 1);

    int acc = 0;
    for (int idx = t; idx < b; idx += SCAN_B) {
        volatile int* p = &agg[idx];
        int a;
        while ((a = *p) == 0) { }
        acc += a - 1;
    }
    __syncthreads();
    s[t] = acc;
    __syncthreads();
#pragma unroll
    for (int off = SCAN_B / 2; off > 0; off >>= 1) {
        if (t < off) s[t] += s[t + off];
        __syncthreads();
    }
    int offset = s[0];
    if (i < N) {
        int r = offset + incl - v;
        row[i] = r;
        cur[i] = r;
    }
    if (i == N) row[N] = E;
}

// ---------------------------------------------------------------------------
__global__ void fill_kernel(const int* __restrict__ src, const int* __restrict__ dst,
                            int* __restrict__ cur, int* __restrict__ csr,
                            int* __restrict__ agg, int E) {
    int i = blockIdx.x * blockDim.x + threadIdx.x;
    if (i < NB_MAX) agg[i] = 0;
    if (i < E) {
        int d = dst[i];
        int p = atomicAdd(&cur[d], 1);
        csr[p] = src[i];
    }
}

// ---------------------------------------------------------------------------
__device__ __forceinline__ void acc_h8(float* acc, uint4 v) {
    float2 f;
    f = __half22float2(*reinterpret_cast<__half2*>(&v.x)); acc[0] += f.x; acc[1] += f.y;
    f = __half22float2(*reinterpret_cast<__half2*>(&v.y)); acc[2] += f.x; acc[3] += f.y;
    f = __half22float2(*reinterpret_cast<__half2*>(&v.z)); acc[4] += f.x; acc[5] += f.y;
    f = __half22float2(*reinterpret_cast<__half2*>(&v.w)); acc[6] += f.x; acc[7] += f.y;
}

// Layer-1 gather: agg = mean(xh[neighbors]). No smem, max occupancy.
__global__ void __launch_bounds__(512)
gather1_kernel(const __half* __restrict__ xh,
               const int*    __restrict__ csr,
               const int*    __restrict__ row,
               __half*       __restrict__ aggh,
               int N) {
    int grp = threadIdx.x >> 3;
    int lane = threadIdx.x & 7;
    int node = blockIdx.x * 64 + grp;
    if (node >= N) node = N - 1;

    int beg = row[node], end = row[node + 1];
    const uint4* xh4 = reinterpret_cast<const uint4*>(xh);

    float acc[8];
#pragma unroll
    for (int i = 0; i < 8; i++) acc[i] = 0.f;

    int e = beg;
    for (; e + 3 < end; e += 4) {
        int s0 = csr[e], s1 = csr[e + 1], s2 = csr[e + 2], s3 = csr[e + 3];
        uint4 v0 = xh4[(size_t)s0 * 8 + lane];
        uint4 v1 = xh4[(size_t)s1 * 8 + lane];
        uint4 v2 = xh4[(size_t)s2 * 8 + lane];
        uint4 v3 = xh4[(size_t)s3 * 8 + lane];
        acc_h8(acc, v0); acc_h8(acc, v1); acc_h8(acc, v2); acc_h8(acc, v3);
    }
    for (; e < end; e++) {
        uint4 v0 = xh4[(size_t)csr[e] * 8 + lane];
        acc_h8(acc, v0);
    }
    float inv = 1.0f / fmaxf((float)(end - beg), 1.0f);
    __half2 h0 = __floats2half2_rn(acc[0] * inv, acc[1] * inv);
    __half2 h1 = __floats2half2_rn(acc[2] * inv, acc[3] * inv);
    __half2 h2 = __floats2half2_rn(acc[4] * inv, acc[5] * inv);
    __half2 h3 = __floats2half2_rn(acc[6] * inv, acc[7] * inv);
    uint4 o;
    o.x = *reinterpret_cast<unsigned int*>(&h0);
    o.y = *reinterpret_cast<unsigned int*>(&h1);
    o.z = *reinterpret_cast<unsigned int*>(&h2);
    o.w = *reinterpret_cast<unsigned int*>(&h3);
    reinterpret_cast<uint4*>(aggh)[(size_t)node * 8 + lane] = o;
}

// ---------------------------------------------------------------------------
// Tensor-core double GEMM: x2t = relu(agg@W1 + b1) @ W2, all via mma.m16n8k16.
// Block = 256 threads (8 warps), 128 nodes (16 per warp).
// GEMM1 C-fragments are re-packed in registers as GEMM2 A-fragments.
#define AS_STRIDE 72   // halves; 144B rows -> conflict-free ldmatrix
__global__ void __launch_bounds__(256)
gemm1_kernel(const __half* __restrict__ aggh,  // [N,64] fp16
             const float*  __restrict__ W1,    // [64,64] (k, j)
             const float*  __restrict__ b1,    // [64]
             const float*  __restrict__ W2,    // [64,32] (k, j)
             __half*       __restrict__ x2th,  // [N,32] fp16
             int N) {
    __shared__ __half As [128][AS_STRIDE];   // agg tile (row-major, padded)
    __shared__ __half Bt1[64][AS_STRIDE];    // W1^T: [n][k]
    __shared__ __half Bt2[32][AS_STRIDE];    // W2^T: [n][k]
    __shared__ float  b1s[D1];

    int tid = threadIdx.x;

    // W1^T, W2^T to fp16 smem
    for (int i = tid; i < D1 * D1; i += 256) {
        int k = i >> 6, n = i & 63;
        Bt1[n][k] = __float2half(W1[i]);
    }
    for (int i = tid; i < D1 * D2; i += 256) {
        int k = i >> 5, n = i & 31;
        Bt2[n][k] = __float2half(W2[i]);
    }
    if (tid < D1) b1s[tid] = b1[tid];

    // agg tile: 128 rows x 64 halves, coalesced uint4 loads
    for (int i = tid; i < 128 * 8; i += 256) {
        int r = i >> 3, ch = i & 7;
        int node = blockIdx.x * 128 + r;
        if (node >= N) node = N - 1;
        uint4 v = reinterpret_cast<const uint4*>(aggh)[(size_t)node * 8 + ch];
        *reinterpret_cast<uint4*>(&As[r][ch * 8]) = v;
    }
    __syncthreads();

    int w = tid >> 5;
    int lane = tid & 31;
    int l16 = lane & 15;

    // ldmatrix source addresses
    unsigned a_base = (unsigned)__cvta_generic_to_shared(
        &As[w * 16 + l16][(lane >> 4) * 8]);
    unsigned b1_base = (unsigned)__cvta_generic_to_shared(
        &Bt1[l16 & 7][(l16 >> 3) * 8]);
    unsigned b2_base = (unsigned)__cvta_generic_to_shared(
        &Bt2[l16 & 7][(l16 >> 3) * 8]);
    const unsigned ROWB = AS_STRIDE * 2;   // bytes per smem row

    float acc2[4][4];
#pragma unroll
    for (int n2 = 0; n2 < 4; n2++)
#pragma unroll
        for (int c = 0; c < 4; c++) acc2[n2][c] = 0.f;

    int qc = (lane & 3) * 2;   // col offset within n8 block

#pragma unroll
    for (int q = 0; q < 4; q++) {          // GEMM1 n-pair block == GEMM2 k-slice
        float c0[4] = {0.f, 0.f, 0.f, 0.f};   // nb = 2q
        float c1[4] = {0.f, 0.f, 0.f, 0.f};   // nb = 2q+1
#pragma unroll
        for (int kt = 0; kt < 4; kt++) {
            unsigned a0, a1, a2, a3, b0, b1r;
            ldsm_x4(a0, a1, a2, a3, a_base + kt * 32);
            ldsm_x2(b0, b1r, b1_base + (2 * q) * 8 * ROWB + kt * 32);
            mma16816(c0, a0, a1, a2, a3, b0, b1r);
            ldsm_x2(b0, b1r, b1_base + (2 * q + 1) * 8 * ROWB + kt * 32);
            mma16816(c1, a0, a1, a2, a3, b0, b1r);
        }
        // bias + relu + repack as GEMM2 A-fragment for k-slice q
        int col = q * 16 + qc;
        float bb0 = b1s[col],     bb1 = b1s[col + 1];
        float bb8 = b1s[col + 8], bb9 = b1s[col + 9];
        unsigned a20 = packh2(fmaxf(c0[0] + bb0, 0.f), fmaxf(c0[1] + bb1, 0.f));
        unsigned a21 = packh2(fmaxf(c0[2] + bb0, 0.f), fmaxf(c0[3] + bb1, 0.f));
        unsigned a22 = packh2(fmaxf(c1[0] + bb8, 0.f), fmaxf(c1[1] + bb9, 0.f));
        unsigned a23 = packh2(fmaxf(c1[2] + bb8, 0.f), fmaxf(c1[3] + bb9, 0.f));
#pragma unroll
        for (int n2 = 0; n2 < 4; n2++) {
            unsigned b0, b1r;
            ldsm_x2(b0, b1r, b2_base + n2 * 8 * ROWB + q * 32);
            mma16816(acc2[n2], a20, a21, a22, a23, b0, b1r);
        }
    }

    // store x2t fragments (fp16)
    int r0 = blockIdx.x * 128 + w * 16 + (lane >> 2);
    int r1 = r0 + 8;
#pragma unroll
    for (int n2 = 0; n2 < 4; n2++) {
        int col = n2 * 8 + qc;
        if (r0 < N) {
            __half2 h = __floats2half2_rn(acc2[n2][0], acc2[n2][1]);
            *reinterpret_cast<__half2*>(x2th + (size_t)r0 * D2 + col) = h;
        }
        if (r1 < N) {
            __half2 h = __floats2half2_rn(acc2[n2][2], acc2[n2][3]);
            *reinterpret_cast<__half2*>(x2th + (size_t)r1 * D2 + col) = h;
        }
    }
}

// ---------------------------------------------------------------------------
// Layer 2 + readout (fp16 gather). 8 lanes per node, 8B per lane.
__global__ void __launch_bounds__(512)
layer2_kernel(const __half* __restrict__ x2th,
              const int*    __restrict__ csr,
              const int*    __restrict__ row,
              const float*  __restrict__ b2,
              const float*  __restrict__ Wd,
              const float*  __restrict__ bd,
              float*        __restrict__ out,
              int N) {
    __shared__ float bs[D2];
    if (threadIdx.x < D2) bs[threadIdx.x] = b2[threadIdx.x];
    __syncthreads();

    int grp = threadIdx.x >> 3;
    int lane = threadIdx.x & 7;
    int node = blockIdx.x * 64 + grp;
    if (node >= N) node = N - 1;

    int beg = row[node], end = row[node + 1];
    const uint2* x2 = reinterpret_cast<const uint2*>(x2th);

    float a0 = 0.f, a1 = 0.f, a2 = 0.f, a3 = 0.f;
    int e = beg;
    for (; e + 3 < end; e += 4) {
        int s0 = csr[e], s1 = csr[e + 1], s2 = csr[e + 2], s3 = csr[e + 3];
        uint2 v0 = x2[(size_t)s0 * 8 + lane];
        uint2 v1 = x2[(size_t)s1 * 8 + lane];
        uint2 v2 = x2[(size_t)s2 * 8 + lane];
        uint2 v3 = x2[(size_t)s3 * 8 + lane];
        float2 f;
        f = __half22float2(*reinterpret_cast<__half2*>(&v0.x)); a0 += f.x; a1 += f.y;
        f = __half22float2(*reinterpret_cast<__half2*>(&v0.y)); a2 += f.x; a3 += f.y;
        f = __half22float2(*reinterpret_cast<__half2*>(&v1.x)); a0 += f.x; a1 += f.y;
        f = __half22float2(*reinterpret_cast<__half2*>(&v1.y)); a2 += f.x; a3 += f.y;
        f = __half22float2(*reinterpret_cast<__half2*>(&v2.x)); a0 += f.x; a1 += f.y;
        f = __half22float2(*reinterpret_cast<__half2*>(&v2.y)); a2 += f.x; a3 += f.y;
        f = __half22float2(*reinterpret_cast<__half2*>(&v3.x)); a0 += f.x; a1 += f.y;
        f = __half22float2(*reinterpret_cast<__half2*>(&v3.y)); a2 += f.x; a3 += f.y;
    }
    for (; e < end; e++) {
        uint2 v0 = x2[(size_t)csr[e] * 8 + lane];
        float2 f;
        f = __half22float2(*reinterpret_cast<__half2*>(&v0.x)); a0 += f.x; a1 += f.y;
        f = __half22float2(*reinterpret_cast<__half2*>(&v0.y)); a2 += f.x; a3 += f.y;
    }
    float inv = 1.0f / fmaxf((float)(end - beg), 1.0f);
    int j = lane * 4;
    float h0 = fmaxf(fmaf(a0, inv, bs[j + 0]), 0.f);
    float h1 = fmaxf(fmaf(a1, inv, bs[j + 1]), 0.f);
    float h2 = fmaxf(fmaf(a2, inv, bs[j + 2]), 0.f);
    float h3 = fmaxf(fmaf(a3, inv, bs[j + 3]), 0.f);

    float v = (h0 + h1) + (h2 + h3);
#pragma unroll
    for (int off = 4; off > 0; off >>= 1)
        v += __shfl_down_sync(0xffffffffu, v, off, 8);

    if (lane == 0) {
        float m = v * (1.0f / (float)D2);
        float z = fmaf(m, Wd[0], bd[0]);
        out[node] = 1.0f / (1.0f + expf(-z));
    }
}

// ---------------------------------------------------------------------------
extern "C" void kernel_launch(void* const* d_in, const int* in_sizes, int n_in,
                              void* d_out, int out_size) {
    const float* x   = (const float*)d_in[0];
    const int*   src = (const int*)  d_in[1];
    const int*   dst = (const int*)  d_in[2];
    const float* W1  = (const float*)d_in[3];
    const float* b1  = (const float*)d_in[4];
    const float* W2  = (const float*)d_in[5];
    const float* b2  = (const float*)d_in[6];
    const float* Wd  = (const float*)d_in[7];
    const float* bd  = (const float*)d_in[8];
    float* out = (float*)d_out;

    const int N = in_sizes[0] / D1;
    const int E = in_sizes[1];

    __half *xh, *aggh, *x2th;
    int *cnt, *row, *cur, *csr, *agg;
    cudaGetSymbolAddress((void**)&xh,   g_xh);
    cudaGetSymbolAddress((void**)&aggh, g_aggh);
    cudaGetSymbolAddress((void**)&x2th, g_x2th);
    cudaGetSymbolAddress((void**)&cnt,  g_cnt);
    cudaGetSymbolAddress((void**)&row,  g_row);
    cudaGetSymbolAddress((void**)&cur,  g_cur);
    cudaGetSymbolAddress((void**)&csr,  g_csr);
    cudaGetSymbolAddress((void**)&agg,  g_agg);

    const int nb = (N + SCAN_B - 1) / SCAN_B;
    const int n4 = N * (D1 / 4);
    const int big = (n4 > E) ? n4 : E;

    conv_hist_kernel<<<(big + 255) / 256, 256>>>(
        reinterpret_cast<const float4*>(x), reinterpret_cast<uint2*>(xh),
        dst, cnt, n4, E);
    scan_kernel<<<nb, SCAN_B>>>(cnt, row, cur, agg, N, E);
    fill_kernel<<<(E + 255) / 256, 256>>>(src, dst, cur, csr, agg, E);

    gather1_kernel<<<(N + 63) / 64, 512>>>(xh, csr, row, aggh, N);
    gemm1_kernel<<<(N + 127) / 128, 256>>>(aggh, W1, b1, W2, x2th, N);
    layer2_kernel<<<(N + 63) / 64, 512>>>(x2th, csr, row, b2, Wd, bd, out, N);
}

// round 12
// speedup vs baseline: 1.4334x; 1.0165x over previous
#include <cuda_runtime.h>
#include <cuda_fp16.h>
#include <cstdint>
#include <math.h>

#define N_NODES_MAX 100000
#define E_MAX       1600000
#define D1 64
#define D2 32
#define SCAN_B 512
#define NB_MAX 256

// Scratch (no allocations allowed)
__device__ __half g_xh  [(size_t)N_NODES_MAX * D1];
__device__ __half g_aggh[(size_t)N_NODES_MAX * D1];
__device__ __half g_x2th[(size_t)N_NODES_MAX * D2];
__device__ int    g_cnt [N_NODES_MAX];   // zeroed by scan (self-restoring)
__device__ int    g_row [N_NODES_MAX + 1];
__device__ int    g_cur [N_NODES_MAX];
__device__ int    g_csr [E_MAX];
__device__ int    g_agg [NB_MAX];        // lookback publish slots (0 = empty)

// ---------------------------------------------------------------------------
// mma / ldmatrix primitives
__device__ __forceinline__ void ldsm_x4(unsigned& a0, unsigned& a1,
                                        unsigned& a2, unsigned& a3, unsigned addr) {
    asm volatile("ldmatrix.sync.aligned.m8n8.x4.shared.b16 {%0,%1,%2,%3}, [%4];"
                 : "=r"(a0), "=r"(a1), "=r"(a2), "=r"(a3) : "r"(addr));
}
__device__ __forceinline__ void ldsm_x2(unsigned& b0, unsigned& b1, unsigned addr) {
    asm volatile("ldmatrix.sync.aligned.m8n8.x2.shared.b16 {%0,%1}, [%2];"
                 : "=r"(b0), "=r"(b1) : "r"(addr));
}
__device__ __forceinline__ void mma16816(float* c,
                                         unsigned a0, unsigned a1, unsigned a2, unsigned a3,
                                         unsigned b0, unsigned b1) {
    asm volatile("mma.sync.aligned.m16n8k16.row.col.f32.f16.f16.f32 "
                 "{%0,%1,%2,%3}, {%4,%5,%6,%7}, {%8,%9}, {%0,%1,%2,%3};"
                 : "+f"(c[0]), "+f"(c[1]), "+f"(c[2]), "+f"(c[3])
                 : "r"(a0), "r"(a1), "r"(a2), "r"(a3), "r"(b0), "r"(b1));
}
__device__ __forceinline__ unsigned packh2(float a, float b) {
    __half2 h = __floats2half2_rn(a, b);
    return *reinterpret_cast<unsigned*>(&h);
}

// fp16 pairwise-add helpers (HADD2)
__device__ __forceinline__ unsigned hadd2u(unsigned a, unsigned b) {
    __half2 r = __hadd2(*reinterpret_cast<__half2*>(&a), *reinterpret_cast<__half2*>(&b));
    return *reinterpret_cast<unsigned*>(&r);
}
__device__ __forceinline__ uint4 hadd2x4(uint4 a, uint4 b) {
    uint4 r;
    r.x = hadd2u(a.x, b.x); r.y = hadd2u(a.y, b.y);
    r.z = hadd2u(a.z, b.z); r.w = hadd2u(a.w, b.w);
    return r;
}
__device__ __forceinline__ uint2 hadd2x2(uint2 a, uint2 b) {
    uint2 r;
    r.x = hadd2u(a.x, b.x); r.y = hadd2u(a.y, b.y);
    return r;
}

// ---------------------------------------------------------------------------
__global__ void conv_hist_kernel(const float4* __restrict__ x4,
                                 uint2* __restrict__ xh,
                                 const int* __restrict__ dst,
                                 int* __restrict__ cnt,
                                 int n4, int E) {
    int i = blockIdx.x * blockDim.x + threadIdx.x;
    if (i < n4) {
        float4 v = x4[i];
        __half2 a = __floats2half2_rn(v.x, v.y);
        __half2 b = __floats2half2_rn(v.z, v.w);
        uint2 o;
        o.x = *reinterpret_cast<unsigned int*>(&a);
        o.y = *reinterpret_cast<unsigned int*>(&b);
        xh[i] = o;
    }
    if (i < E) atomicAdd(&cnt[dst[i]], 1);
}

// ---------------------------------------------------------------------------
__global__ void __launch_bounds__(SCAN_B)
scan_kernel(int* __restrict__ cnt, int* __restrict__ row, int* __restrict__ cur,
            int* __restrict__ agg, int N, int E) {
    __shared__ int s[SCAN_B];
    int t = threadIdx.x;
    int b = blockIdx.x;
    int i = b * SCAN_B + t;
    int v = (i < N) ? cnt[i] : 0;
    if (i < N) cnt[i] = 0;
    s[t] = v;
    __syncthreads();
#pragma unroll
    for (int off = 1; off < SCAN_B; off <<= 1) {
        int u = 0;
        if (t >= off) u = s[t - off];
        __syncthreads();
        if (t >= off) s[t] += u;
        __syncthreads();
    }
    int incl = s[t];
    if (t == 0) atomicExch(&agg[b], s[SCAN_B - 1] + 1);

    int acc = 0;
    for (int idx = t; idx < b; idx += SCAN_B) {
        volatile int* p = &agg[idx];
        int a;
        while ((a = *p) == 0) { }
        acc += a - 1;
    }
    __syncthreads();
    s[t] = acc;
    __syncthreads();
#pragma unroll
    for (int off = SCAN_B / 2; off > 0; off >>= 1) {
        if (t < off) s[t] += s[t + off];
        __syncthreads();
    }
    int offset = s[0];
    if (i < N) {
        int r = offset + incl - v;
        row[i] = r;
        cur[i] = r;
    }
    if (i == N) row[N] = E;
}

// ---------------------------------------------------------------------------
__global__ void fill_kernel(const int* __restrict__ src, const int* __restrict__ dst,
                            int* __restrict__ cur, int* __restrict__ csr,
                            int* __restrict__ agg, int E) {
    int i = blockIdx.x * blockDim.x + threadIdx.x;
    if (i < NB_MAX) agg[i] = 0;
    if (i < E) {
        int d = dst[i];
        int p = atomicAdd(&cur[d], 1);
        csr[p] = src[i];
    }
}

// ---------------------------------------------------------------------------
__device__ __forceinline__ void acc_h8(float* acc, uint4 v) {
    float2 f;
    f = __half22float2(*reinterpret_cast<__half2*>(&v.x)); acc[0] += f.x; acc[1] += f.y;
    f = __half22float2(*reinterpret_cast<__half2*>(&v.y)); acc[2] += f.x; acc[3] += f.y;
    f = __half22float2(*reinterpret_cast<__half2*>(&v.z)); acc[4] += f.x; acc[5] += f.y;
    f = __half22float2(*reinterpret_cast<__half2*>(&v.w)); acc[6] += f.x; acc[7] += f.y;
}

// Layer-1 gather: agg = mean(xh[neighbors]). fp16 depth-2 pairwise tree,
// fp32 master accumulator. 8 lanes per node, no smem.
__global__ void __launch_bounds__(512)
gather1_kernel(const __half* __restrict__ xh,
               const int*    __restrict__ csr,
               const int*    __restrict__ row,
               __half*       __restrict__ aggh,
               int N) {
    int grp = threadIdx.x >> 3;
    int lane = threadIdx.x & 7;
    int node = blockIdx.x * 64 + grp;
    if (node >= N) node = N - 1;

    int beg = row[node], end = row[node + 1];
    const uint4* xh4 = reinterpret_cast<const uint4*>(xh);

    float acc[8];
#pragma unroll
    for (int i = 0; i < 8; i++) acc[i] = 0.f;

    int e = beg;
    for (; e + 3 < end; e += 4) {
        int s0 = csr[e], s1 = csr[e + 1], s2 = csr[e + 2], s3 = csr[e + 3];
        uint4 v0 = xh4[(size_t)s0 * 8 + lane];
        uint4 v1 = xh4[(size_t)s1 * 8 + lane];
        uint4 v2 = xh4[(size_t)s2 * 8 + lane];
        uint4 v3 = xh4[(size_t)s3 * 8 + lane];
        uint4 s01 = hadd2x4(v0, v1);
        uint4 s23 = hadd2x4(v2, v3);
        acc_h8(acc, hadd2x4(s01, s23));
    }
    for (; e < end; e++) {
        uint4 v0 = xh4[(size_t)csr[e] * 8 + lane];
        acc_h8(acc, v0);
    }
    float inv = 1.0f / fmaxf((float)(end - beg), 1.0f);
    __half2 h0 = __floats2half2_rn(acc[0] * inv, acc[1] * inv);
    __half2 h1 = __floats2half2_rn(acc[2] * inv, acc[3] * inv);
    __half2 h2 = __floats2half2_rn(acc[4] * inv, acc[5] * inv);
    __half2 h3 = __floats2half2_rn(acc[6] * inv, acc[7] * inv);
    uint4 o;
    o.x = *reinterpret_cast<unsigned int*>(&h0);
    o.y = *reinterpret_cast<unsigned int*>(&h1);
    o.z = *reinterpret_cast<unsigned int*>(&h2);
    o.w = *reinterpret_cast<unsigned int*>(&h3);
    reinterpret_cast<uint4*>(aggh)[(size_t)node * 8 + lane] = o;
}

// ---------------------------------------------------------------------------
// Tensor-core double GEMM: x2t = relu(agg@W1 + b1) @ W2 via mma.m16n8k16.
// Block = 256 threads (8 warps), 128 nodes. GEMM1 C-frags repacked in regs
// as GEMM2 A-frags (no smem round trip).
#define AS_STRIDE 72   // halves; 144B rows -> conflict-free ldmatrix
__global__ void __launch_bounds__(256)
gemm1_kernel(const __half* __restrict__ aggh,  // [N,64] fp16
             const float*  __restrict__ W1,    // [64,64] (k, j)
             const float*  __restrict__ b1,    // [64]
             const float*  __restrict__ W2,    // [64,32] (k, j)
             __half*       __restrict__ x2th,  // [N,32] fp16
             int N) {
    __shared__ __half As [128][AS_STRIDE];
    __shared__ __half Bt1[64][AS_STRIDE];    // W1^T: [n][k]
    __shared__ __half Bt2[32][AS_STRIDE];    // W2^T: [n][k]
    __shared__ float  b1s[D1];

    int tid = threadIdx.x;

    for (int i = tid; i < D1 * D1; i += 256) {
        int k = i >> 6, n = i & 63;
        Bt1[n][k] = __float2half(W1[i]);
    }
    for (int i = tid; i < D1 * D2; i += 256) {
        int k = i >> 5, n = i & 31;
        Bt2[n][k] = __float2half(W2[i]);
    }
    if (tid < D1) b1s[tid] = b1[tid];

    for (int i = tid; i < 128 * 8; i += 256) {
        int r = i >> 3, ch = i & 7;
        int node = blockIdx.x * 128 + r;
        if (node >= N) node = N - 1;
        uint4 v = reinterpret_cast<const uint4*>(aggh)[(size_t)node * 8 + ch];
        *reinterpret_cast<uint4*>(&As[r][ch * 8]) = v;
    }
    __syncthreads();

    int w = tid >> 5;
    int lane = tid & 31;
    int l16 = lane & 15;

    unsigned a_base = (unsigned)__cvta_generic_to_shared(
        &As[w * 16 + l16][(lane >> 4) * 8]);
    unsigned b1_base = (unsigned)__cvta_generic_to_shared(
        &Bt1[l16 & 7][(l16 >> 3) * 8]);
    unsigned b2_base = (unsigned)__cvta_generic_to_shared(
        &Bt2[l16 & 7][(l16 >> 3) * 8]);
    const unsigned ROWB = AS_STRIDE * 2;

    float acc2[4][4];
#pragma unroll
    for (int n2 = 0; n2 < 4; n2++)
#pragma unroll
        for (int c = 0; c < 4; c++) acc2[n2][c] = 0.f;

    int qc = (lane & 3) * 2;

#pragma unroll
    for (int q = 0; q < 4; q++) {
        float c0[4] = {0.f, 0.f, 0.f, 0.f};
        float c1[4] = {0.f, 0.f, 0.f, 0.f};
#pragma unroll
        for (int kt = 0; kt < 4; kt++) {
            unsigned a0, a1, a2, a3, b0, b1r;
            ldsm_x4(a0, a1, a2, a3, a_base + kt * 32);
            ldsm_x2(b0, b1r, b1_base + (2 * q) * 8 * ROWB + kt * 32);
            mma16816(c0, a0, a1, a2, a3, b0, b1r);
            ldsm_x2(b0, b1r, b1_base + (2 * q + 1) * 8 * ROWB + kt * 32);
            mma16816(c1, a0, a1, a2, a3, b0, b1r);
        }
        int col = q * 16 + qc;
        float bb0 = b1s[col],     bb1 = b1s[col + 1];
        float bb8 = b1s[col + 8], bb9 = b1s[col + 9];
        unsigned a20 = packh2(fmaxf(c0[0] + bb0, 0.f), fmaxf(c0[1] + bb1, 0.f));
        unsigned a21 = packh2(fmaxf(c0[2] + bb0, 0.f), fmaxf(c0[3] + bb1, 0.f));
        unsigned a22 = packh2(fmaxf(c1[0] + bb8, 0.f), fmaxf(c1[1] + bb9, 0.f));
        unsigned a23 = packh2(fmaxf(c1[2] + bb8, 0.f), fmaxf(c1[3] + bb9, 0.f));
#pragma unroll
        for (int n2 = 0; n2 < 4; n2++) {
            unsigned b0, b1r;
            ldsm_x2(b0, b1r, b2_base + n2 * 8 * ROWB + q * 32);
            mma16816(acc2[n2], a20, a21, a22, a23, b0, b1r);
        }
    }

    int r0 = blockIdx.x * 128 + w * 16 + (lane >> 2);
    int r1 = r0 + 8;
#pragma unroll
    for (int n2 = 0; n2 < 4; n2++) {
        int col = n2 * 8 + qc;
        if (r0 < N) {
            __half2 h = __floats2half2_rn(acc2[n2][0], acc2[n2][1]);
            *reinterpret_cast<__half2*>(x2th + (size_t)r0 * D2 + col) = h;
        }
        if (r1 < N) {
            __half2 h = __floats2half2_rn(acc2[n2][2], acc2[n2][3]);
            *reinterpret_cast<__half2*>(x2th + (size_t)r1 * D2 + col) = h;
        }
    }
}

// ---------------------------------------------------------------------------
// Layer 2 + readout: fp16 depth-2 pairwise gather tree, fp32 master acc.
__global__ void __launch_bounds__(512)
layer2_kernel(const __half* __restrict__ x2th,
              const int*    __restrict__ csr,
              const int*    __restrict__ row,
              const float*  __restrict__ b2,
              const float*  __restrict__ Wd,
              const float*  __restrict__ bd,
              float*        __restrict__ out,
              int N) {
    __shared__ float bs[D2];
    if (threadIdx.x < D2) bs[threadIdx.x] = b2[threadIdx.x];
    __syncthreads();

    int grp = threadIdx.x >> 3;
    int lane = threadIdx.x & 7;
    int node = blockIdx.x * 64 + grp;
    if (node >= N) node = N - 1;

    int beg = row[node], end = row[node + 1];
    const uint2* x2 = reinterpret_cast<const uint2*>(x2th);

    float a0 = 0.f, a1 = 0.f, a2 = 0.f, a3 = 0.f;
    int e = beg;
    for (; e + 3 < end; e += 4) {
        int s0 = csr[e], s1 = csr[e + 1], s2 = csr[e + 2], s3 = csr[e + 3];
        uint2 v0 = x2[(size_t)s0 * 8 + lane];
        uint2 v1 = x2[(size_t)s1 * 8 + lane];
        uint2 v2 = x2[(size_t)s2 * 8 + lane];
        uint2 v3 = x2[(size_t)s3 * 8 + lane];
        uint2 s01 = hadd2x2(v0, v1);
        uint2 s23 = hadd2x2(v2, v3);
        uint2 s = hadd2x2(s01, s23);
        float2 f;
        f = __half22float2(*reinterpret_cast<__half2*>(&s.x)); a0 += f.x; a1 += f.y;
        f = __half22float2(*reinterpret_cast<__half2*>(&s.y)); a2 += f.x; a3 += f.y;
    }
    for (; e < end; e++) {
        uint2 v0 = x2[(size_t)csr[e] * 8 + lane];
        float2 f;
        f = __half22float2(*reinterpret_cast<__half2*>(&v0.x)); a0 += f.x; a1 += f.y;
        f = __half22float2(*reinterpret_cast<__half2*>(&v0.y)); a2 += f.x; a3 += f.y;
    }
    float inv = 1.0f / fmaxf((float)(end - beg), 1.0f);
    int j = lane * 4;
    float h0 = fmaxf(fmaf(a0, inv, bs[j + 0]), 0.f);
    float h1 = fmaxf(fmaf(a1, inv, bs[j + 1]), 0.f);
    float h2 = fmaxf(fmaf(a2, inv, bs[j + 2]), 0.f);
    float h3 = fmaxf(fmaf(a3, inv, bs[j + 3]), 0.f);

    float v = (h0 + h1) + (h2 + h3);
#pragma unroll
    for (int off = 4; off > 0; off >>= 1)
        v += __shfl_down_sync(0xffffffffu, v, off, 8);

    if (lane == 0) {
        float m = v * (1.0f / (float)D2);
        float z = fmaf(m, Wd[0], bd[0]);
        out[node] = 1.0f / (1.0f + expf(-z));
    }
}

// ---------------------------------------------------------------------------
extern "C" void kernel_launch(void* const* d_in, const int* in_sizes, int n_in,
                              void* d_out, int out_size) {
    const float* x   = (const float*)d_in[0];
    const int*   src = (const int*)  d_in[1];
    const int*   dst = (const int*)  d_in[2];
    const float* W1  = (const float*)d_in[3];
    const float* b1  = (const float*)d_in[4];
    const float* W2  = (const float*)d_in[5];
    const float* b2  = (const float*)d_in[6];
    const float* Wd  = (const float*)d_in[7];
    const float* bd  = (const float*)d_in[8];
    float* out = (float*)d_out;

    const int N = in_sizes[0] / D1;
    const int E = in_sizes[1];

    __half *xh, *aggh, *x2th;
    int *cnt, *row, *cur, *csr, *agg;
    cudaGetSymbolAddress((void**)&xh,   g_xh);
    cudaGetSymbolAddress((void**)&aggh, g_aggh);
    cudaGetSymbolAddress((void**)&x2th, g_x2th);
    cudaGetSymbolAddress((void**)&cnt,  g_cnt);
    cudaGetSymbolAddress((void**)&row,  g_row);
    cudaGetSymbolAddress((void**)&cur,  g_cur);
    cudaGetSymbolAddress((void**)&csr,  g_csr);
    cudaGetSymbolAddress((void**)&agg,  g_agg);

    const int nb = (N + SCAN_B - 1) / SCAN_B;
    const int n4 = N * (D1 / 4);
    const int big = (n4 > E) ? n4 : E;

    conv_hist_kernel<<<(big + 255) / 256, 256>>>(
        reinterpret_cast<const float4*>(x), reinterpret_cast<uint2*>(xh),
        dst, cnt, n4, E);
    scan_kernel<<<nb, SCAN_B>>>(cnt, row, cur, agg, N, E);
    fill_kernel<<<(E + 255) / 256, 256>>>(src, dst, cur, csr, agg, E);

    gather1_kernel<<<(N + 63) / 64, 512>>>(xh, csr, row, aggh, N);
    gemm1_kernel<<<(N + 127) / 128, 256>>>(aggh, W1, b1, W2, x2th, N);
    layer2_kernel<<<(N + 63) / 64, 512>>>(x2th, csr, row, b2, Wd, bd, out, N);
}